// round 6
// baseline (speedup 1.0000x reference)
#include <cuda_runtime.h>
#include <math.h>

// Problem constants
#define BDIM 4
#define SDIM 2048
#define DDIM 1024
#define HDIM 16
#define DHD  64
#define FDIM 4096
#define MROWS (BDIM * SDIM)   // 8192

// ---------------------------------------------------------------------------
// Scratch (static device globals; no allocation allowed in kernel_launch)
// ---------------------------------------------------------------------------
__device__ float g_q   [MROWS * DDIM];   // Q proj, later reused: ---
__device__ float g_k   [MROWS * DDIM];   // K proj, later reused for attn_out
__device__ float g_v   [MROWS * DDIM];   // V proj
__device__ float g_ctx [MROWS * DDIM];   // attention context
__device__ float g_out1[MROWS * DDIM];   // LN1 output
__device__ float g_ffn [MROWS * FDIM];   // FFN hidden (ReLU applied)
__device__ float g_ffn2[MROWS * DDIM];   // FFN output

// ---------------------------------------------------------------------------
// SGEMM: C[M,N] = A[M,K] @ W[K,N] + bias  (optional ReLU)
// 128x128 block tile, BK=16, 256 threads, 8x8 per thread,
// double-buffered shared memory with register prefetch.
// All dims are multiples of the tile sizes here -> no bounds checks.
// ---------------------------------------------------------------------------
template <bool RELU>
__global__ __launch_bounds__(256)
void sgemm_bias(const float* __restrict__ A, const float* __restrict__ W,
                const float* __restrict__ bias, float* __restrict__ C,
                int M, int N, int K)
{
    constexpr int BM = 128, BN = 128, BK = 16;
    __shared__ float As[2][BK][BM];
    __shared__ float Bs[2][BK][BN];

    const int tid = threadIdx.x;
    const int tx  = tid & 15;       // 0..15  -> 8 output cols each
    const int ty  = tid >> 4;       // 0..15  -> 8 output rows each
    const int bm  = blockIdx.y * BM;
    const int bn  = blockIdx.x * BN;

    // A tile load mapping: 128 rows x 16 cols = 512 float4; 2 per thread
    const int a_row = tid >> 2;          // 0..63 (second at +64)
    const int a_col = (tid & 3) << 2;    // 0,4,8,12
    // B tile load mapping: 16 rows x 128 cols = 512 float4; 2 per thread
    const int b_row = tid >> 5;          // 0..7 (second at +8)
    const int b_col = (tid & 31) << 2;   // 0..124

    const float* Ap = A + (size_t)(bm + a_row) * K + a_col;
    const float* Bp = W + (size_t)b_row * N + (bn + b_col);

    // Prime buffer 0
    float4 ra0 = *(const float4*)(Ap);
    float4 ra1 = *(const float4*)(Ap + (size_t)64 * K);
    float4 rb0 = *(const float4*)(Bp);
    float4 rb1 = *(const float4*)(Bp + (size_t)8 * N);

    As[0][a_col + 0][a_row]      = ra0.x;
    As[0][a_col + 1][a_row]      = ra0.y;
    As[0][a_col + 2][a_row]      = ra0.z;
    As[0][a_col + 3][a_row]      = ra0.w;
    As[0][a_col + 0][a_row + 64] = ra1.x;
    As[0][a_col + 1][a_row + 64] = ra1.y;
    As[0][a_col + 2][a_row + 64] = ra1.z;
    As[0][a_col + 3][a_row + 64] = ra1.w;
    *(float4*)&Bs[0][b_row][b_col]     = rb0;
    *(float4*)&Bs[0][b_row + 8][b_col] = rb1;
    __syncthreads();

    float acc[8][8];
    #pragma unroll
    for (int i = 0; i < 8; i++)
        #pragma unroll
        for (int j = 0; j < 8; j++) acc[i][j] = 0.f;

    const int NT = K / BK;
    for (int kt = 0; kt < NT; kt++) {
        const int cur = kt & 1;

        // Prefetch next tile into registers (hides GMEM latency under FMAs)
        if (kt + 1 < NT) {
            const float* Ap2 = Ap + (size_t)(kt + 1) * BK;
            ra0 = *(const float4*)(Ap2);
            ra1 = *(const float4*)(Ap2 + (size_t)64 * K);
            const float* Bp2 = Bp + (size_t)(kt + 1) * BK * N;
            rb0 = *(const float4*)(Bp2);
            rb1 = *(const float4*)(Bp2 + (size_t)8 * N);
        }

        #pragma unroll
        for (int kk = 0; kk < BK; kk++) {
            float af[8], bf[8];
            *(float4*)&af[0] = *(const float4*)&As[cur][kk][ty * 8];
            *(float4*)&af[4] = *(const float4*)&As[cur][kk][ty * 8 + 4];
            *(float4*)&bf[0] = *(const float4*)&Bs[cur][kk][tx * 8];
            *(float4*)&bf[4] = *(const float4*)&Bs[cur][kk][tx * 8 + 4];
            #pragma unroll
            for (int i = 0; i < 8; i++)
                #pragma unroll
                for (int j = 0; j < 8; j++)
                    acc[i][j] = fmaf(af[i], bf[j], acc[i][j]);
        }

        if (kt + 1 < NT) {
            const int nxt = cur ^ 1;
            As[nxt][a_col + 0][a_row]      = ra0.x;
            As[nxt][a_col + 1][a_row]      = ra0.y;
            As[nxt][a_col + 2][a_row]      = ra0.z;
            As[nxt][a_col + 3][a_row]      = ra0.w;
            As[nxt][a_col + 0][a_row + 64] = ra1.x;
            As[nxt][a_col + 1][a_row + 64] = ra1.y;
            As[nxt][a_col + 2][a_row + 64] = ra1.z;
            As[nxt][a_col + 3][a_row + 64] = ra1.w;
            *(float4*)&Bs[nxt][b_row][b_col]     = rb0;
            *(float4*)&Bs[nxt][b_row + 8][b_col] = rb1;
        }
        __syncthreads();
    }

    // Epilogue: bias (+ ReLU), vectorized stores
    float bv[8];
    *(float4*)&bv[0] = *(const float4*)&bias[bn + tx * 8];
    *(float4*)&bv[4] = *(const float4*)&bias[bn + tx * 8 + 4];

    #pragma unroll
    for (int i = 0; i < 8; i++) {
        float4 o0, o1;
        o0.x = acc[i][0] + bv[0];  o0.y = acc[i][1] + bv[1];
        o0.z = acc[i][2] + bv[2];  o0.w = acc[i][3] + bv[3];
        o1.x = acc[i][4] + bv[4];  o1.y = acc[i][5] + bv[5];
        o1.z = acc[i][6] + bv[6];  o1.w = acc[i][7] + bv[7];
        if (RELU) {
            o0.x = fmaxf(o0.x, 0.f); o0.y = fmaxf(o0.y, 0.f);
            o0.z = fmaxf(o0.z, 0.f); o0.w = fmaxf(o0.w, 0.f);
            o1.x = fmaxf(o1.x, 0.f); o1.y = fmaxf(o1.y, 0.f);
            o1.z = fmaxf(o1.z, 0.f); o1.w = fmaxf(o1.w, 0.f);
        }
        float* cp = C + (size_t)(bm + ty * 8 + i) * N + (bn + tx * 8);
        *(float4*)cp       = o0;
        *(float4*)(cp + 4) = o1;
    }
}

// ---------------------------------------------------------------------------
// Flash attention (fp32, no S x S materialization).
// Layout: Q/K/V are [B*S, D] with head h at columns [h*64, h*64+64).
// One thread owns one q-row; K/V tiles of 64 x 64 staged in SMEM (broadcast
// reads). Online softmax with branch-deferred rescale (rescale only on a
// new running max, which is O(log S) times per row).
// ---------------------------------------------------------------------------
__global__ __launch_bounds__(128)
void flash_attn(const float* __restrict__ Q, const float* __restrict__ K,
                const float* __restrict__ V, float* __restrict__ O)
{
    constexpr int BC = 64;
    __shared__ float Ks[BC][DHD];
    __shared__ float Vs[BC][DHD];

    const int t = threadIdx.x;
    const int b = blockIdx.z;
    const int h = blockIdx.y;
    const int qrow = blockIdx.x * 128 + t;

    const float scale = 0.125f;  // 1/sqrt(64)
    const float* qptr = Q + ((size_t)(b * SDIM + qrow)) * DDIM + h * DHD;

    float qr[DHD];
    #pragma unroll
    for (int i = 0; i < DHD; i += 4) {
        float4 v4 = *(const float4*)(qptr + i);
        qr[i]     = v4.x * scale;
        qr[i + 1] = v4.y * scale;
        qr[i + 2] = v4.z * scale;
        qr[i + 3] = v4.w * scale;
    }

    float o[DHD];
    #pragma unroll
    for (int i = 0; i < DHD; i++) o[i] = 0.f;
    float m = -1e30f, l = 0.f;

    const float* kbase0 = K + (size_t)b * SDIM * DDIM + h * DHD;
    const float* vbase0 = V + (size_t)b * SDIM * DDIM + h * DHD;

    for (int kt = 0; kt < SDIM / BC; kt++) {
        __syncthreads();  // previous tile fully consumed
        const float* kb = kbase0 + (size_t)kt * BC * DDIM;
        const float* vb = vbase0 + (size_t)kt * BC * DDIM;
        #pragma unroll
        for (int idx = t; idx < BC * DHD / 4; idx += 128) {
            const int r = idx >> 4;
            const int c = idx & 15;
            ((float4*)Ks)[idx] = *((const float4*)(kb + (size_t)r * DDIM) + c);
            ((float4*)Vs)[idx] = *((const float4*)(vb + (size_t)r * DDIM) + c);
        }
        __syncthreads();

        #pragma unroll 1
        for (int j = 0; j < BC; j++) {
            float s0 = 0.f, s1 = 0.f, s2 = 0.f, s3 = 0.f;
            #pragma unroll
            for (int kk = 0; kk < DHD; kk += 4) {
                s0 = fmaf(qr[kk + 0], Ks[j][kk + 0], s0);
                s1 = fmaf(qr[kk + 1], Ks[j][kk + 1], s1);
                s2 = fmaf(qr[kk + 2], Ks[j][kk + 2], s2);
                s3 = fmaf(qr[kk + 3], Ks[j][kk + 3], s3);
            }
            const float s = (s0 + s1) + (s2 + s3);
            if (s > m) {
                const float corr = __expf(m - s);
                l *= corr;
                #pragma unroll
                for (int d = 0; d < DHD; d++) o[d] *= corr;
                m = s;
            }
            const float p = __expf(s - m);
            l += p;
            #pragma unroll
            for (int d = 0; d < DHD; d++)
                o[d] = fmaf(p, Vs[j][d], o[d]);
        }
    }

    const float inv = 1.0f / l;
    float* optr = O + ((size_t)(b * SDIM + qrow)) * DDIM + h * DHD;
    #pragma unroll
    for (int i = 0; i < DHD; i += 4) {
        float4 v4;
        v4.x = o[i] * inv;     v4.y = o[i + 1] * inv;
        v4.z = o[i + 2] * inv; v4.w = o[i + 3] * inv;
        *(float4*)(optr + i) = v4;
    }
}

// ---------------------------------------------------------------------------
// out = LayerNorm(a + b) * g + beta   (one block per row of D=1024)
// ---------------------------------------------------------------------------
__global__ __launch_bounds__(256)
void add_ln(const float* __restrict__ a, const float* __restrict__ bsrc,
            const float* __restrict__ g, const float* __restrict__ be,
            float* __restrict__ out)
{
    __shared__ float ss[8], ssq[8];
    const int row = blockIdx.x;
    const int t = threadIdx.x;
    const size_t base = (size_t)row * DDIM;

    float4 va = ((const float4*)(a + base))[t];
    float4 vb = ((const float4*)(bsrc + base))[t];
    const float v0 = va.x + vb.x;
    const float v1 = va.y + vb.y;
    const float v2 = va.z + vb.z;
    const float v3 = va.w + vb.w;

    float s  = v0 + v1 + v2 + v3;
    float sq = v0 * v0 + v1 * v1 + v2 * v2 + v3 * v3;
    #pragma unroll
    for (int off = 16; off; off >>= 1) {
        s  += __shfl_xor_sync(0xffffffffu, s, off);
        sq += __shfl_xor_sync(0xffffffffu, sq, off);
    }
    if ((t & 31) == 0) { ss[t >> 5] = s; ssq[t >> 5] = sq; }
    __syncthreads();
    float S = 0.f, SQ = 0.f;
    #pragma unroll
    for (int w = 0; w < 8; w++) { S += ss[w]; SQ += ssq[w]; }

    const float mean = S * (1.0f / DDIM);
    const float var  = SQ * (1.0f / DDIM) - mean * mean;
    const float rstd = rsqrtf(var + 1e-6f);

    float4 vg  = ((const float4*)g)[t];
    float4 vbe = ((const float4*)be)[t];
    float4 r;
    r.x = (v0 - mean) * rstd * vg.x + vbe.x;
    r.y = (v1 - mean) * rstd * vg.y + vbe.y;
    r.z = (v2 - mean) * rstd * vg.z + vbe.z;
    r.w = (v3 - mean) * rstd * vg.w + vbe.w;
    ((float4*)(out + base))[t] = r;
}

// ---------------------------------------------------------------------------
// kernel_launch: graph-capturable sequence on the default stream
// ---------------------------------------------------------------------------
extern "C" void kernel_launch(void* const* d_in, const int* in_sizes, int n_in,
                              void* d_out, int out_size)
{
    const float* x   = (const float*)d_in[0];
    const float* wq  = (const float*)d_in[1];
    const float* bq  = (const float*)d_in[2];
    const float* wk  = (const float*)d_in[3];
    const float* bk  = (const float*)d_in[4];
    const float* wv  = (const float*)d_in[5];
    const float* bv  = (const float*)d_in[6];
    const float* wo  = (const float*)d_in[7];
    const float* bo  = (const float*)d_in[8];
    const float* w1  = (const float*)d_in[9];
    const float* b1  = (const float*)d_in[10];
    const float* w2  = (const float*)d_in[11];
    const float* b2  = (const float*)d_in[12];
    const float* g1  = (const float*)d_in[13];
    const float* be1 = (const float*)d_in[14];
    const float* g2  = (const float*)d_in[15];
    const float* be2 = (const float*)d_in[16];

    float *q, *k, *v, *ctx, *out1, *ffn, *ffn2;
    cudaGetSymbolAddress((void**)&q,    g_q);
    cudaGetSymbolAddress((void**)&k,    g_k);
    cudaGetSymbolAddress((void**)&v,    g_v);
    cudaGetSymbolAddress((void**)&ctx,  g_ctx);
    cudaGetSymbolAddress((void**)&out1, g_out1);
    cudaGetSymbolAddress((void**)&ffn,  g_ffn);
    cudaGetSymbolAddress((void**)&ffn2, g_ffn2);

    const dim3 gProjD(DDIM / 128, MROWS / 128);   // N=1024 projections
    const dim3 gProjF(FDIM / 128, MROWS / 128);   // N=4096 FFN1

    // QKV projections
    sgemm_bias<false><<<gProjD, 256>>>(x, wq, bq, q, MROWS, DDIM, DDIM);
    sgemm_bias<false><<<gProjD, 256>>>(x, wk, bk, k, MROWS, DDIM, DDIM);
    sgemm_bias<false><<<gProjD, 256>>>(x, wv, bv, v, MROWS, DDIM, DDIM);

    // Attention
    flash_attn<<<dim3(SDIM / 128, HDIM, BDIM), 128>>>(q, k, v, ctx);

    // Output projection (reuse g_k as attn_out scratch)
    sgemm_bias<false><<<gProjD, 256>>>(ctx, wo, bo, k, MROWS, DDIM, DDIM);

    // Residual + LN1
    add_ln<<<MROWS, 256>>>(x, k, g1, be1, out1);

    // FFN
    sgemm_bias<true ><<<gProjF, 256>>>(out1, w1, b1, ffn,  MROWS, FDIM, DDIM);
    sgemm_bias<false><<<gProjD, 256>>>(ffn,  w2, b2, ffn2, MROWS, DDIM, FDIM);

    // Residual + LN2 -> final output
    add_ln<<<MROWS, 256>>>(out1, ffn2, g2, be2, (float*)d_out);
}

// round 8
// speedup vs baseline: 1.5047x; 1.5047x over previous
#include <cuda_runtime.h>
#include <cuda_bf16.h>
#include <math.h>

// Problem constants
#define BDIM 4
#define SDIM 2048
#define DDIM 1024
#define HDIM 16
#define DHD  64
#define FDIM 4096
#define MROWS (BDIM * SDIM)   // 8192

typedef unsigned long long ull;

// ---------------------------------------------------------------------------
// Scratch (static device globals; no allocation allowed in kernel_launch)
// ---------------------------------------------------------------------------
__device__ float g_q   [MROWS * DDIM];
__device__ float g_k   [MROWS * DDIM];   // K proj, later reused for attn_out
__device__ float g_v   [MROWS * DDIM];
__device__ float g_ctx [MROWS * DDIM];
__device__ float g_out1[MROWS * DDIM];
__device__ float g_ffn [MROWS * FDIM];
__device__ float g_ffn2[MROWS * DDIM];

// ---------------------------------------------------------------------------
// Packed f32x2 helpers (sm_100+): 2 independent fp32 FMAs per issue slot.
// ---------------------------------------------------------------------------
__device__ __forceinline__ ull f2pack(float lo, float hi) {
    ull r; asm("mov.b64 %0, {%1,%2};" : "=l"(r) : "f"(lo), "f"(hi)); return r;
}
__device__ __forceinline__ void f2unpack(ull v, float& lo, float& hi) {
    asm("mov.b64 {%0,%1}, %2;" : "=f"(lo), "=f"(hi) : "l"(v));
}
__device__ __forceinline__ ull ffma2(ull a, ull b, ull c) {
    ull d; asm("fma.rn.f32x2 %0, %1, %2, %3;" : "=l"(d) : "l"(a), "l"(b), "l"(c));
    return d;
}
__device__ __forceinline__ ull fmul2(ull a, ull b) {
    ull d; asm("mul.rn.f32x2 %0, %1, %2;" : "=l"(d) : "l"(a), "l"(b));
    return d;
}

// ---------------------------------------------------------------------------
// bf16 split helpers for tensor-core GEMM.
// hi = truncated-bf16 pair (one PRMT), lo = rounded residual pair.
// a = hi + lo up to ~2^-17 relative; dropped lo*lo term <= 2^-16 relative.
// ---------------------------------------------------------------------------
__device__ __forceinline__ void split2(float f0, float f1, unsigned& hi, unsigned& lo) {
    unsigned u0 = __float_as_uint(f0);
    unsigned u1 = __float_as_uint(f1);
    hi = __byte_perm(u0, u1, 0x7632);           // {bf_trunc(f0) lo16, bf_trunc(f1) hi16}
    float r0 = f0 - __uint_as_float(u0 & 0xFFFF0000u);
    float r1 = f1 - __uint_as_float(u1 & 0xFFFF0000u);
    asm("cvt.rn.bf16x2.f32 %0, %1, %2;" : "=r"(lo) : "f"(r1), "f"(r0));  // lo16=r0
}

__device__ __forceinline__ void mma16816(float* c, const unsigned* a, const unsigned* b) {
    asm volatile(
        "mma.sync.aligned.m16n8k16.row.col.f32.bf16.bf16.f32 "
        "{%0,%1,%2,%3}, {%4,%5,%6,%7}, {%8,%9}, {%0,%1,%2,%3};"
        : "+f"(c[0]), "+f"(c[1]), "+f"(c[2]), "+f"(c[3])
        : "r"(a[0]), "r"(a[1]), "r"(a[2]), "r"(a[3]), "r"(b[0]), "r"(b[1]));
}

// ---------------------------------------------------------------------------
// Tensor-core GEMM with bf16 3-pass split precision.
// C[M,N] = A[M,K] @ W[K,N] + bias (optional ReLU). fp32 in/out.
// Block tile 128x128, BK=32, 256 threads (8 warps as 2m x 4n),
// each warp: 64x32 via 4x4 m16n8k16 fragments, 3 MMA passes (hh, hl, lh).
// SMEM: packed bf16x2 words, padded pitch PW=20 words -> fragment LDS.32
// loads are bank-conflict-free (row*20 mod 32 hits {0,4,...,28}).
// ---------------------------------------------------------------------------
template <bool RELU>
__global__ __launch_bounds__(256)
void hgemm_bias(const float* __restrict__ A, const float* __restrict__ W,
                const float* __restrict__ bias, float* __restrict__ C,
                int M, int N, int K)
{
    constexpr int BM = 128, BN = 128, BK = 32;
    constexpr int PW = 20;  // padded words per row (BK/2 = 16 data + 4 pad)
    __shared__ unsigned sAh[BM * PW];
    __shared__ unsigned sAl[BM * PW];
    __shared__ unsigned sBh[BN * PW];
    __shared__ unsigned sBl[BN * PW];

    const int tid  = threadIdx.x;
    const int warp = tid >> 5;
    const int lane = tid & 31;
    const int bm = blockIdx.y * BM;
    const int bn = blockIdx.x * BN;

    const int g = lane >> 2;   // 0..7
    const int t = lane & 3;    // 0..3
    const int wm = warp >> 2;  // 0..1 : 64-row slab
    const int wn = warp & 3;   // 0..3 : 32-col slab

    // B staging mapping: n = lane + 32*(warp&3); k half: warps 0-3 -> k[0,16), 4-7 -> k[16,32)
    const int b_n  = lane + 32 * (warp & 3);
    const int b_k0 = (warp >> 2) * 16;

    const float* Abase = A + (size_t)bm * K;
    const float* Wbase = W + bn + b_n;

    float4 ra[4];
    float  rb[16];

    // ---- prime tile 0 ----
    {
        #pragma unroll
        for (int i = 0; i < 4; i++) {
            const int idx = tid + 256 * i;
            const int row = idx >> 3, c4 = idx & 7;
            ra[i] = *(const float4*)(Abase + (size_t)row * K + c4 * 4);
        }
        const float* wp = Wbase + (size_t)b_k0 * N;
        #pragma unroll
        for (int i = 0; i < 8; i++) {
            rb[2 * i]     = wp[(size_t)(2 * i) * N];
            rb[2 * i + 1] = wp[(size_t)(2 * i + 1) * N];
        }
        #pragma unroll
        for (int i = 0; i < 4; i++) {
            const int idx = tid + 256 * i;
            const int row = idx >> 3, c4 = idx & 7;
            unsigned h, l;
            split2(ra[i].x, ra[i].y, h, l);
            sAh[row * PW + 2 * c4]     = h;  sAl[row * PW + 2 * c4]     = l;
            split2(ra[i].z, ra[i].w, h, l);
            sAh[row * PW + 2 * c4 + 1] = h;  sAl[row * PW + 2 * c4 + 1] = l;
        }
        #pragma unroll
        for (int i = 0; i < 8; i++) {
            unsigned h, l;
            split2(rb[2 * i], rb[2 * i + 1], h, l);
            sBh[b_n * PW + b_k0 / 2 + i] = h;
            sBl[b_n * PW + b_k0 / 2 + i] = l;
        }
    }
    __syncthreads();

    float acc[4][4][4];
    #pragma unroll
    for (int mf = 0; mf < 4; mf++)
        #pragma unroll
        for (int nf = 0; nf < 4; nf++)
            #pragma unroll
            for (int r = 0; r < 4; r++) acc[mf][nf][r] = 0.f;

    const int NT = K / BK;
    for (int kt = 0; kt < NT; kt++) {
        // prefetch next tile (gmem -> regs) while computing current
        if (kt + 1 < NT) {
            const int koff = (kt + 1) * BK;
            #pragma unroll
            for (int i = 0; i < 4; i++) {
                const int idx = tid + 256 * i;
                const int row = idx >> 3, c4 = idx & 7;
                ra[i] = *(const float4*)(Abase + (size_t)row * K + koff + c4 * 4);
            }
            const float* wp = Wbase + (size_t)(koff + b_k0) * N;
            #pragma unroll
            for (int i = 0; i < 8; i++) {
                rb[2 * i]     = wp[(size_t)(2 * i) * N];
                rb[2 * i + 1] = wp[(size_t)(2 * i + 1) * N];
            }
        }

        // ---- compute: 2 k-steps of 16 ----
        #pragma unroll
        for (int ks = 0; ks < 2; ks++) {
            const int kw = ks * 8;
            unsigned ah[4][4], al_[4][4], bh[4][2], bl[4][2];
            #pragma unroll
            for (int mf = 0; mf < 4; mf++) {
                const int r0 = wm * 64 + mf * 16 + g;
                ah[mf][0]  = sAh[r0 * PW + kw + t];
                ah[mf][1]  = sAh[(r0 + 8) * PW + kw + t];
                ah[mf][2]  = sAh[r0 * PW + kw + t + 4];
                ah[mf][3]  = sAh[(r0 + 8) * PW + kw + t + 4];
                al_[mf][0] = sAl[r0 * PW + kw + t];
                al_[mf][1] = sAl[(r0 + 8) * PW + kw + t];
                al_[mf][2] = sAl[r0 * PW + kw + t + 4];
                al_[mf][3] = sAl[(r0 + 8) * PW + kw + t + 4];
            }
            #pragma unroll
            for (int nf = 0; nf < 4; nf++) {
                const int nb = wn * 32 + nf * 8 + g;
                bh[nf][0] = sBh[nb * PW + kw + t];
                bh[nf][1] = sBh[nb * PW + kw + t + 4];
                bl[nf][0] = sBl[nb * PW + kw + t];
                bl[nf][1] = sBl[nb * PW + kw + t + 4];
            }
            #pragma unroll
            for (int mf = 0; mf < 4; mf++)
                #pragma unroll
                for (int nf = 0; nf < 4; nf++) {
                    mma16816(acc[mf][nf], ah[mf],  bh[nf]);
                    mma16816(acc[mf][nf], ah[mf],  bl[nf]);
                    mma16816(acc[mf][nf], al_[mf], bh[nf]);
                }
        }
        __syncthreads();

        if (kt + 1 < NT) {
            #pragma unroll
            for (int i = 0; i < 4; i++) {
                const int idx = tid + 256 * i;
                const int row = idx >> 3, c4 = idx & 7;
                unsigned h, l;
                split2(ra[i].x, ra[i].y, h, l);
                sAh[row * PW + 2 * c4]     = h;  sAl[row * PW + 2 * c4]     = l;
                split2(ra[i].z, ra[i].w, h, l);
                sAh[row * PW + 2 * c4 + 1] = h;  sAl[row * PW + 2 * c4 + 1] = l;
            }
            #pragma unroll
            for (int i = 0; i < 8; i++) {
                unsigned h, l;
                split2(rb[2 * i], rb[2 * i + 1], h, l);
                sBh[b_n * PW + b_k0 / 2 + i] = h;
                sBl[b_n * PW + b_k0 / 2 + i] = l;
            }
        }
        __syncthreads();
    }

    // ---- epilogue: bias (+ReLU), float2 stores (full 32B sectors) ----
    #pragma unroll
    for (int nf = 0; nf < 4; nf++) {
        const int col = bn + wn * 32 + nf * 8 + 2 * t;
        const float2 bv = *(const float2*)(bias + col);
        #pragma unroll
        for (int mf = 0; mf < 4; mf++) {
            const int row = bm + wm * 64 + mf * 16 + g;
            float2 v0, v1;
            v0.x = acc[mf][nf][0] + bv.x;  v0.y = acc[mf][nf][1] + bv.y;
            v1.x = acc[mf][nf][2] + bv.x;  v1.y = acc[mf][nf][3] + bv.y;
            if (RELU) {
                v0.x = fmaxf(v0.x, 0.f); v0.y = fmaxf(v0.y, 0.f);
                v1.x = fmaxf(v1.x, 0.f); v1.y = fmaxf(v1.y, 0.f);
            }
            *(float2*)(C + (size_t)row * N + col)       = v0;
            *(float2*)(C + (size_t)(row + 8) * N + col) = v1;
        }
    }
}

// ---------------------------------------------------------------------------
// Flash attention, fp32 exact, inner loops on packed f32x2 FMA (FFMA2).
// One thread = one q row; K/V tiles 64x64 in SMEM (broadcast LDS.64).
// ---------------------------------------------------------------------------
__global__ __launch_bounds__(128)
void flash_attn(const float* __restrict__ Q, const float* __restrict__ K,
                const float* __restrict__ V, float* __restrict__ O)
{
    constexpr int BC = 64;
    __shared__ __align__(16) float Ks[BC][DHD];
    __shared__ __align__(16) float Vs[BC][DHD];

    const int t = threadIdx.x;
    const int b = blockIdx.z;
    const int h = blockIdx.y;
    const int qrow = blockIdx.x * 128 + t;

    const float scale = 0.125f;  // 1/sqrt(64)
    const float* qptr = Q + ((size_t)(b * SDIM + qrow)) * DDIM + h * DHD;

    ull q2[DHD / 2];
    #pragma unroll
    for (int i = 0; i < DHD; i += 4) {
        float4 v4 = *(const float4*)(qptr + i);
        q2[i / 2]     = f2pack(v4.x * scale, v4.y * scale);
        q2[i / 2 + 1] = f2pack(v4.z * scale, v4.w * scale);
    }

    ull o2[DHD / 2];
    #pragma unroll
    for (int i = 0; i < DHD / 2; i++) o2[i] = 0ULL;
    float m = -1e30f, l = 0.f;

    const float* kbase0 = K + (size_t)b * SDIM * DDIM + h * DHD;
    const float* vbase0 = V + (size_t)b * SDIM * DDIM + h * DHD;

    for (int kt = 0; kt < SDIM / BC; kt++) {
        __syncthreads();
        const float* kb = kbase0 + (size_t)kt * BC * DDIM;
        const float* vb = vbase0 + (size_t)kt * BC * DDIM;
        #pragma unroll
        for (int idx = t; idx < BC * DHD / 4; idx += 128) {
            const int r = idx >> 4;
            const int c = idx & 15;
            ((float4*)Ks)[idx] = *((const float4*)(kb + (size_t)r * DDIM) + c);
            ((float4*)Vs)[idx] = *((const float4*)(vb + (size_t)r * DDIM) + c);
        }
        __syncthreads();

        #pragma unroll 1
        for (int j = 0; j < BC; j++) {
            const ull* K2 = (const ull*)Ks[j];
            ull a0 = 0ULL, a1 = 0ULL, a2 = 0ULL, a3 = 0ULL;
            #pragma unroll
            for (int w = 0; w < DHD / 2; w += 4) {
                a0 = ffma2(q2[w],     K2[w],     a0);
                a1 = ffma2(q2[w + 1], K2[w + 1], a1);
                a2 = ffma2(q2[w + 2], K2[w + 2], a2);
                a3 = ffma2(q2[w + 3], K2[w + 3], a3);
            }
            float s;
            {
                float x0, x1, x2, x3, x4, x5, x6, x7;
                f2unpack(a0, x0, x1); f2unpack(a1, x2, x3);
                f2unpack(a2, x4, x5); f2unpack(a3, x6, x7);
                s = ((x0 + x1) + (x2 + x3)) + ((x4 + x5) + (x6 + x7));
            }
            if (s > m) {
                const float corr = __expf(m - s);
                const ull corr2 = f2pack(corr, corr);
                l *= corr;
                #pragma unroll
                for (int w = 0; w < DHD / 2; w++) o2[w] = fmul2(o2[w], corr2);
                m = s;
            }
            const float p = __expf(s - m);
            l += p;
            const ull p2 = f2pack(p, p);
            const ull* V2 = (const ull*)Vs[j];
            #pragma unroll
            for (int w = 0; w < DHD / 2; w++)
                o2[w] = ffma2(p2, V2[w], o2[w]);
        }
    }

    const float inv = 1.0f / l;
    float* optr = O + ((size_t)(b * SDIM + qrow)) * DDIM + h * DHD;
    #pragma unroll
    for (int w = 0; w < DHD / 2; w += 2) {
        float4 v4;
        float lo0, hi0, lo1, hi1;
        f2unpack(o2[w], lo0, hi0);
        f2unpack(o2[w + 1], lo1, hi1);
        v4.x = lo0 * inv; v4.y = hi0 * inv;
        v4.z = lo1 * inv; v4.w = hi1 * inv;
        *(float4*)(optr + 2 * w) = v4;
    }
}

// ---------------------------------------------------------------------------
// out = LayerNorm(a + b) * g + beta   (one block per row of D=1024)
// ---------------------------------------------------------------------------
__global__ __launch_bounds__(256)
void add_ln(const float* __restrict__ a, const float* __restrict__ bsrc,
            const float* __restrict__ g, const float* __restrict__ be,
            float* __restrict__ out)
{
    __shared__ float ss[8], ssq[8];
    const int row = blockIdx.x;
    const int t = threadIdx.x;
    const size_t base = (size_t)row * DDIM;

    float4 va = ((const float4*)(a + base))[t];
    float4 vb = ((const float4*)(bsrc + base))[t];
    const float v0 = va.x + vb.x;
    const float v1 = va.y + vb.y;
    const float v2 = va.z + vb.z;
    const float v3 = va.w + vb.w;

    float s  = v0 + v1 + v2 + v3;
    float sq = v0 * v0 + v1 * v1 + v2 * v2 + v3 * v3;
    #pragma unroll
    for (int off = 16; off; off >>= 1) {
        s  += __shfl_xor_sync(0xffffffffu, s, off);
        sq += __shfl_xor_sync(0xffffffffu, sq, off);
    }
    if ((t & 31) == 0) { ss[t >> 5] = s; ssq[t >> 5] = sq; }
    __syncthreads();
    float S = 0.f, SQ = 0.f;
    #pragma unroll
    for (int w = 0; w < 8; w++) { S += ss[w]; SQ += ssq[w]; }

    const float mean = S * (1.0f / DDIM);
    const float var  = SQ * (1.0f / DDIM) - mean * mean;
    const float rstd = rsqrtf(var + 1e-6f);

    float4 vg  = ((const float4*)g)[t];
    float4 vbe = ((const float4*)be)[t];
    float4 r;
    r.x = (v0 - mean) * rstd * vg.x + vbe.x;
    r.y = (v1 - mean) * rstd * vg.y + vbe.y;
    r.z = (v2 - mean) * rstd * vg.z + vbe.z;
    r.w = (v3 - mean) * rstd * vg.w + vbe.w;
    ((float4*)(out + base))[t] = r;
}

// ---------------------------------------------------------------------------
// kernel_launch: graph-capturable sequence on the default stream
// ---------------------------------------------------------------------------
extern "C" void kernel_launch(void* const* d_in, const int* in_sizes, int n_in,
                              void* d_out, int out_size)
{
    const float* x   = (const float*)d_in[0];
    const float* wq  = (const float*)d_in[1];
    const float* bq  = (const float*)d_in[2];
    const float* wk  = (const float*)d_in[3];
    const float* bk  = (const float*)d_in[4];
    const float* wv  = (const float*)d_in[5];
    const float* bv  = (const float*)d_in[6];
    const float* wo  = (const float*)d_in[7];
    const float* bo  = (const float*)d_in[8];
    const float* w1  = (const float*)d_in[9];
    const float* b1  = (const float*)d_in[10];
    const float* w2  = (const float*)d_in[11];
    const float* b2  = (const float*)d_in[12];
    const float* g1  = (const float*)d_in[13];
    const float* be1 = (const float*)d_in[14];
    const float* g2  = (const float*)d_in[15];
    const float* be2 = (const float*)d_in[16];

    float *q, *k, *v, *ctx, *out1, *ffn, *ffn2;
    cudaGetSymbolAddress((void**)&q,    g_q);
    cudaGetSymbolAddress((void**)&k,    g_k);
    cudaGetSymbolAddress((void**)&v,    g_v);
    cudaGetSymbolAddress((void**)&ctx,  g_ctx);
    cudaGetSymbolAddress((void**)&out1, g_out1);
    cudaGetSymbolAddress((void**)&ffn,  g_ffn);
    cudaGetSymbolAddress((void**)&ffn2, g_ffn2);

    const dim3 gProjD(DDIM / 128, MROWS / 128);   // N=1024 GEMMs
    const dim3 gProjF(FDIM / 128, MROWS / 128);   // N=4096 FFN1

    // QKV projections (tensor cores, bf16 3-pass split)
    hgemm_bias<false><<<gProjD, 256>>>(x, wq, bq, q, MROWS, DDIM, DDIM);
    hgemm_bias<false><<<gProjD, 256>>>(x, wk, bk, k, MROWS, DDIM, DDIM);
    hgemm_bias<false><<<gProjD, 256>>>(x, wv, bv, v, MROWS, DDIM, DDIM);

    // Attention (fp32 exact, f32x2 packed FMA)
    flash_attn<<<dim3(SDIM / 128, HDIM, BDIM), 128>>>(q, k, v, ctx);

    // Output projection (reuse g_k as attn_out scratch)
    hgemm_bias<false><<<gProjD, 256>>>(ctx, wo, bo, k, MROWS, DDIM, DDIM);

    // Residual + LN1
    add_ln<<<MROWS, 256>>>(x, k, g1, be1, out1);

    // FFN
    hgemm_bias<true ><<<gProjF, 256>>>(out1, w1, b1, ffn,  MROWS, FDIM, DDIM);
    hgemm_bias<false><<<gProjD, 256>>>(ffn,  w2, b2, ffn2, MROWS, DDIM, FDIM);

    // Residual + LN2 -> final output
    add_ln<<<MROWS, 256>>>(out1, ffn2, g2, be2, (float*)d_out);
}